// round 16
// baseline (speedup 1.0000x reference)
#include <cuda_runtime.h>
#include <cuda_fp16.h>
#include <math.h>

#define BB 8
#define TT 2048
#define CC 384
#define HH 64

// Scratch (allocation-free rule: __device__ globals). NO P matrix.
__device__ __half g_qh[BB * TT * HH];               // 2 MB  [b][t][h]
__device__ __half g_kh[BB * TT * HH];               // 2 MB  [b][s][h]
__device__ __half g_vT[BB * HH * TT];               // 2 MB  [b][h][s], scaled by 1/Z
__device__ float  g_sum[BB * TT];                   // per-key exp sums

// ---------------------------------------------------------------------------
// fp16 m16n8k16 MMA + ldmatrix + cp.async helpers. g = lane>>2, tg = lane&3.
//  A row-major [m][k]: a0=(g,2tg) a1=(g+8,2tg) a2=(g,2tg+8) a3=(g+8,2tg+8)
//  B col-major [n][k]: b0=(n g, k 2tg) b1=(n g, k 2tg+8)
//  C: c0=(g,2tg) c1=(g,2tg+1) c2=(g+8,2tg) c3=(g+8,2tg+1)
// ---------------------------------------------------------------------------
__device__ __forceinline__ void mma16(float* c, const unsigned* a, const unsigned* b) {
    asm("mma.sync.aligned.m16n8k16.row.col.f32.f16.f16.f32 "
        "{%0,%1,%2,%3},{%4,%5,%6,%7},{%8,%9},{%0,%1,%2,%3};"
        : "+f"(c[0]), "+f"(c[1]), "+f"(c[2]), "+f"(c[3])
        : "r"(a[0]), "r"(a[1]), "r"(a[2]), "r"(a[3]), "r"(b[0]), "r"(b[1]));
}

__device__ __forceinline__ void ldsm_x4(unsigned* r, unsigned addr) {
    asm volatile("ldmatrix.sync.aligned.m8n8.x4.shared.b16 {%0,%1,%2,%3}, [%4];"
                 : "=r"(r[0]), "=r"(r[1]), "=r"(r[2]), "=r"(r[3]) : "r"(addr));
}

__device__ __forceinline__ unsigned smaddr(const void* p) {
    return (unsigned)__cvta_generic_to_shared(p);
}

__device__ __forceinline__ void cp16(unsigned dst, const void* src) {
    asm volatile("cp.async.cg.shared.global [%0], [%1], 16;" :: "r"(dst), "l"(src));
}
#define CP_COMMIT() asm volatile("cp.async.commit_group;")
#define CP_WAIT0()  asm volatile("cp.async.wait_group 0;")
#define CP_WAIT1()  asm volatile("cp.async.wait_group 1;")

// A-operand x4 base (16 rows x 16 k): matrices (r0,k0),(r+8,k0),(r0,k+8),(r+8,k+8)
#define A_OFF(lane) ((((lane) & 7) + (((lane) >> 3) & 1) * 8) )
#define A_KOFF(lane) ((((lane) >> 4) & 1) * 8)
// B-operand x4 base (16 n-rows x 16 k): matrices (n0,k0),(n0,k+8),(n+8,k0),(n+8,k+8)
#define B_OFF(lane) ((((lane) & 7) + (((lane) >> 4) & 1) * 8))
#define B_KOFF(lane) ((((lane) >> 3) & 1) * 8)

#define HS 72   // half stride for 64-col k tiles (144 B rows, 16B aligned, cf)
#define PS 40   // half stride for 32-col k tiles (80 B rows, 16B aligned, cf)

// ---------------------------------------------------------------------------
// Kernel 1: fused projections, fp16 MMA. Also zeroes g_sum (first 64 y==0
// blocks). q -> g_qh[t][h], k -> g_kh[s][h], v -> g_vT[h][s].
// grid = (B*T/64, 3), block = 256.
// ---------------------------------------------------------------------------
__global__ void proj_kernel(const float* __restrict__ x,
                            const float* __restrict__ Wq,
                            const float* __restrict__ Wk,
                            const float* __restrict__ Wv) {
    __shared__ __align__(16) __half xs[64 * PS];  // [m][k32]
    __shared__ __align__(16) __half ws[64 * PS];  // [n][k32] (W transposed)
    const int tid = threadIdx.x;
    if (blockIdx.y == 0 && blockIdx.x < 64)
        g_sum[blockIdx.x * 256 + tid] = 0.f;
    const float* W = (blockIdx.y == 0) ? Wq : (blockIdx.y == 1) ? Wk : Wv;
    const int row0 = blockIdx.x * 64;
    const int lane = tid & 31, wid = tid >> 5;
    const int g = lane >> 2, tg = lane & 3;
    const int mw = (wid & 1) * 32, nw = (wid >> 1) * 16;

    unsigned aab[2], bab;
    {
        const int ar = A_OFF(lane), ak = A_KOFF(lane);
        aab[0] = smaddr(&xs[(mw + ar) * PS + ak]);
        aab[1] = smaddr(&xs[(mw + 16 + ar) * PS + ak]);
        bab = smaddr(&ws[(nw + B_OFF(lane)) * PS + B_KOFF(lane)]);
    }

    float acc[2][2][4] = {};
    for (int k0c = 0; k0c < CC; k0c += 32) {
#pragma unroll
        for (int i = tid; i < 512; i += 256) {   // x: 64 m x 32 k
            int r = i >> 3, c4 = (i & 7) * 4;
            float4 v = *(const float4*)&x[(size_t)(row0 + r) * CC + k0c + c4];
            *(__half2*)&xs[r * PS + c4]     = __floats2half2_rn(v.x, v.y);
            *(__half2*)&xs[r * PS + c4 + 2] = __floats2half2_rn(v.z, v.w);
        }
#pragma unroll
        for (int i = tid; i < 512; i += 256) {   // W: 32 k x 64 n -> transpose
            int r = i >> 4, c4 = (i & 15) * 4;
            float4 v = *(const float4*)&W[(k0c + r) * HH + c4];
            ws[(c4 + 0) * PS + r] = __float2half(v.x);
            ws[(c4 + 1) * PS + r] = __float2half(v.y);
            ws[(c4 + 2) * PS + r] = __float2half(v.z);
            ws[(c4 + 3) * PS + r] = __float2half(v.w);
        }
        __syncthreads();
#pragma unroll
        for (int kk = 0; kk < 2; kk++) {         // two k16 steps
            unsigned a[2][4], bq[4];
            ldsm_x4(a[0], aab[0] + kk * 32);
            ldsm_x4(a[1], aab[1] + kk * 32);
            ldsm_x4(bq, bab + kk * 32);
#pragma unroll
            for (int mt = 0; mt < 2; mt++)
#pragma unroll
                for (int nt = 0; nt < 2; nt++)
                    mma16(acc[mt][nt], a[mt], bq + nt * 2);
        }
        __syncthreads();
    }

    __half* outqk = (blockIdx.y == 0) ? g_qh : g_kh;
#pragma unroll
    for (int mt = 0; mt < 2; mt++)
#pragma unroll
        for (int rs = 0; rs < 2; rs++) {
            const int row = row0 + mw + mt * 16 + rs * 8 + g;
#pragma unroll
            for (int nt = 0; nt < 2; nt++) {
                const int col = nw + nt * 8 + 2 * tg;
                const float v0 = acc[mt][nt][rs * 2], v1 = acc[mt][nt][rs * 2 + 1];
                if (blockIdx.y < 2) {
                    *(__half2*)&outqk[(size_t)row * HH + col] = __floats2half2_rn(v0, v1);
                } else {
                    const int s = row & (TT - 1);
                    const size_t hb = (size_t)(row >> 11) * HH;
                    g_vT[(hb + col) * TT + s]     = __float2half(v0);
                    g_vT[(hb + col + 1) * TT + s] = __float2half(v1);
                }
            }
        }
}

// ---------------------------------------------------------------------------
// Kernel 2: sumexp. Z[s] += sum_{t>=s} exp(scale*q[t].k[s]). NO P store.
// fp16 MMA + ldmatrix + cp.async, 128x128 tiles. m=t, n=s, k=h.
// grid = (T/128, T/128, B), block 256, dyn smem 36864B (2+ blocks/SM).
// Warps: 2 t-groups (64 rows) x 4 s-groups (32 cols).
// ---------------------------------------------------------------------------
__global__ void __launch_bounds__(256, 2) sumexp_kernel(float scale) {
    const int t0 = blockIdx.x * 128;
    const int s0 = blockIdx.y * 128;
    if (t0 + 127 < s0) return;
    const int b = blockIdx.z;
    extern __shared__ __align__(16) __half sm[];
    __half* qs = sm;              // [128][HS]
    __half* ks = sm + 128 * HS;   // [128][HS]
    const __half* qb = g_qh + (size_t)b * TT * HH;
    const __half* kb = g_kh + (size_t)b * TT * HH;
    const int tid = threadIdx.x;
    const unsigned qsa = smaddr(qs), ksa = smaddr(ks);
#pragma unroll
    for (int i = tid; i < 1024; i += 256) {
        int r = i >> 3, j = (i & 7) * 8;
        cp16(qsa + (r * HS + j) * 2, &qb[(size_t)(t0 + r) * HH + j]);
        cp16(ksa + (r * HS + j) * 2, &kb[(size_t)(s0 + r) * HH + j]);
    }
    CP_COMMIT();
    CP_WAIT0();
    __syncthreads();
    const int lane = tid & 31, wid = tid >> 5;
    const int g = lane >> 2, tg = lane & 3;
    const int tw = (wid & 1) * 64, sw = (wid >> 1) * 32;

    unsigned aab[4], bab[2];
    {
        const int ar = A_OFF(lane), ak = A_KOFF(lane);
        const int br = B_OFF(lane), bk = B_KOFF(lane);
#pragma unroll
        for (int mt = 0; mt < 4; mt++)
            aab[mt] = smaddr(&qs[(tw + mt * 16 + ar) * HS + ak]);
#pragma unroll
        for (int np = 0; np < 2; np++)
            bab[np] = smaddr(&ks[(sw + np * 16 + br) * HS + bk]);
    }

    float acc[4][4][4] = {};  // [mt(t)][nt(s)][4]
#pragma unroll
    for (int k4 = 0; k4 < 4; k4++) {
        unsigned a[4][4], bq[2][4];
#pragma unroll
        for (int mt = 0; mt < 4; mt++) ldsm_x4(a[mt], aab[mt] + k4 * 32);
#pragma unroll
        for (int np = 0; np < 2; np++) ldsm_x4(bq[np], bab[np] + k4 * 32);
#pragma unroll
        for (int mt = 0; mt < 4; mt++)
#pragma unroll
            for (int nt = 0; nt < 4; nt++)
                mma16(acc[mt][nt], a[mt], bq[nt >> 1] + (nt & 1) * 2);
    }

    float* Zb = g_sum + b * TT;
    float zc[4][2] = {};
#pragma unroll
    for (int mt = 0; mt < 4; mt++)
#pragma unroll
        for (int rs = 0; rs < 2; rs++) {
            const int t = t0 + tw + mt * 16 + rs * 8 + g;
#pragma unroll
            for (int nt = 0; nt < 4; nt++) {
                const int s = s0 + sw + nt * 8 + 2 * tg;
                if (t >= s) zc[nt][0] += __expf(acc[mt][nt][rs * 2] * scale);
                if (t >  s) zc[nt][1] += __expf(acc[mt][nt][rs * 2 + 1] * scale);
            }
        }
#pragma unroll
    for (int nt = 0; nt < 4; nt++) {
        float z0 = zc[nt][0], z1 = zc[nt][1];
#pragma unroll
        for (int o = 4; o < 32; o <<= 1) {
            z0 += __shfl_xor_sync(0xffffffffu, z0, o);
            z1 += __shfl_xor_sync(0xffffffffu, z1, o);
        }
        if (g == 0) {
            const int s = s0 + sw + nt * 8 + 2 * tg;
            atomicAdd(&Zb[s], z0);
            atomicAdd(&Zb[s + 1], z1);
        }
    }
}

// ---------------------------------------------------------------------------
// Kernel 3: scale vT in place by 1/Z[s]; also zeroes d_out for attn's atomics.
// grid = 512, block = 256 (one uint4 = 8 halves per thread).
// ---------------------------------------------------------------------------
__global__ void normalize_kernel(float* __restrict__ out) {
    const int u = blockIdx.x * 256 + threadIdx.x;   // uint4 index
    const float4 z = make_float4(0.f, 0.f, 0.f, 0.f);
    ((float4*)out)[u * 2]     = z;
    ((float4*)out)[u * 2 + 1] = z;
    const int hl = u * 8;
    const int bh = hl >> 11;            // b*64 + h
    const int s = hl & (TT - 1);
    const float* Zp = g_sum + ((bh >> 6) << 11) + s;
    uint4 val = *(uint4*)&g_vT[(size_t)bh * TT + s];
    __half2* hp = (__half2*)&val;
    const float4 z0 = *(const float4*)&Zp[0];
    const float4 z1 = *(const float4*)&Zp[4];
    float2 f;
    f = __half22float2(hp[0]);
    hp[0] = __floats2half2_rn(f.x * __frcp_rn(z0.x), f.y * __frcp_rn(z0.y));
    f = __half22float2(hp[1]);
    hp[1] = __floats2half2_rn(f.x * __frcp_rn(z0.z), f.y * __frcp_rn(z0.w));
    f = __half22float2(hp[2]);
    hp[2] = __floats2half2_rn(f.x * __frcp_rn(z1.x), f.y * __frcp_rn(z1.y));
    f = __half22float2(hp[3]);
    hp[3] = __floats2half2_rn(f.x * __frcp_rn(z1.z), f.y * __frcp_rn(z1.w));
    *(uint4*)&g_vT[(size_t)bh * TT + s] = val;
}

// ---------------------------------------------------------------------------
// Kernel 4: fused QK-recompute + exp + PV. P exists only in smem.
// Per s-tile: QK MMA (q smem, k cp.async) -> masked exp in regs -> stage P
// tile [64][HS] -> PV MMA (P x pre-scaled vT). 3-stage k/v pipeline.
// grid = (T/64 t, 4 s-chunks of 8 tiles, B), block 256, dyn smem 73728B.
// Warps: 4 t-groups (16 rows); QK n-split = s (2x32), PV n-split = h (2x32).
// ---------------------------------------------------------------------------
#define AST 3
__global__ void __launch_bounds__(256, 2) attn_kernel(float* __restrict__ out,
                                                      float scale) {
    const int tt = blockIdx.x;
    const int chunk0 = blockIdx.y * 8;
    if (chunk0 > tt) return;
    const int t0 = tt * 64;
    const int b = blockIdx.z;
    const __half* qb = g_qh + (size_t)b * TT * HH;
    const __half* kb = g_kh + (size_t)b * TT * HH;
    const __half* vTb = g_vT + (size_t)b * HH * TT;

    extern __shared__ __align__(16) __half sm[];
    __half* qs  = sm;                        // [64][HS]
    __half* Pst = sm + 64 * HS;              // [64][HS] staged P
    __half* ks  = sm + 2 * 64 * HS;          // AST x [64][HS]
    __half* vs  = sm + (2 + AST) * 64 * HS;  // AST x [64][HS]
    const unsigned qsa = smaddr(qs), ksa = smaddr(ks), vsa = smaddr(vs);
    const unsigned BUF = 64 * HS * 2;        // bytes per stage

    const int tid = threadIdx.x;
    const int lane = tid & 31, wid = tid >> 5;
    const int g = lane >> 2, tg = lane & 3;
    const int tw = (wid >> 1) * 16;          // t rows of this warp
    const int sq = (wid & 1) * 32;           // QK s-cols of this warp
    const int hw = (wid & 1) * 32;           // PV h-cols of this warp

    unsigned qa, kba[2], pa, vba[2];
    {
        const int ar = A_OFF(lane), ak = A_KOFF(lane);
        const int br = B_OFF(lane), bk = B_KOFF(lane);
        qa = smaddr(&qs[(tw + ar) * HS + ak]);
        pa = smaddr(&Pst[(tw + ar) * HS + ak]);
#pragma unroll
        for (int np = 0; np < 2; np++) {
            kba[np] = smaddr(&ks[(sq + np * 16 + br) * HS + bk]);
            vba[np] = smaddr(&vs[(hw + np * 16 + br) * HS + bk]);
        }
    }

    const int n = min(chunk0 + 8, tt + 1) - chunk0;

    // q fill (once) + stage 0 k/v, then stage 1.
#pragma unroll
    for (int i = tid; i < 512; i += 256) {
        int r = i >> 3, j = (i & 7) * 8;
        cp16(qsa + (r * HS + j) * 2, &qb[(size_t)(t0 + r) * HH + j]);
        int s0 = chunk0 * 64;
        cp16(ksa + (r * HS + j) * 2, &kb[(size_t)(s0 + r) * HH + j]);
        cp16(vsa + (r * HS + j) * 2, &vTb[(size_t)r * TT + s0 + j]);
    }
    CP_COMMIT();
    if (n > 1) {
#pragma unroll
        for (int i = tid; i < 512; i += 256) {
            int r = i >> 3, j = (i & 7) * 8;
            int s0 = (chunk0 + 1) * 64;
            cp16(ksa + BUF + (r * HS + j) * 2, &kb[(size_t)(s0 + r) * HH + j]);
            cp16(vsa + BUF + (r * HS + j) * 2, &vTb[(size_t)r * TT + s0 + j]);
        }
    }
    CP_COMMIT();

    float acc_o[4][4] = {};  // [nt(h)][4], accumulated over all s-tiles
    for (int st = 0; st < n; st++) {
        const unsigned boff = (unsigned)(st % AST) * BUF;
        const int s0 = (chunk0 + st) * 64;
        CP_WAIT1();
        __syncthreads();  // stage ready; prior PV reads of Pst done

        // QK MMA: m=t(16/warp), n=s(32/warp), k=h(64)
        float accs[4][4] = {};
#pragma unroll
        for (int k4 = 0; k4 < 4; k4++) {
            unsigned a[4], bq[2][4];
            ldsm_x4(a, qa + k4 * 32);
            ldsm_x4(bq[0], kba[0] + boff + k4 * 32);
            ldsm_x4(bq[1], kba[1] + boff + k4 * 32);
#pragma unroll
            for (int nt = 0; nt < 4; nt++)
                mma16(accs[nt], a, bq[nt >> 1] + (nt & 1) * 2);
        }

        // exp + mask -> staged P tile (vT pre-scaled, so no invZ here)
        {
            const int tr0 = t0 + tw + g, tr1 = tr0 + 8;
#pragma unroll
            for (int nt = 0; nt < 4; nt++) {
                const int sl = sq + nt * 8 + 2 * tg;
                const int s = s0 + sl;
                float e0 = (tr0 >= s)     ? __expf(accs[nt][0] * scale) : 0.f;
                float e1 = (tr0 >= s + 1) ? __expf(accs[nt][1] * scale) : 0.f;
                float e2 = (tr1 >= s)     ? __expf(accs[nt][2] * scale) : 0.f;
                float e3 = (tr1 >= s + 1) ? __expf(accs[nt][3] * scale) : 0.f;
                *(__half2*)&Pst[(tw + g) * HS + sl]     = __floats2half2_rn(e0, e1);
                *(__half2*)&Pst[(tw + g + 8) * HS + sl] = __floats2half2_rn(e2, e3);
            }
        }

        // prefetch stage st+2
        if (st + 2 < n) {
            const unsigned foff = (unsigned)((st + 2) % AST) * BUF;
            const int sf = (chunk0 + st + 2) * 64;
#pragma unroll
            for (int i = tid; i < 512; i += 256) {
                int r = i >> 3, j = (i & 7) * 8;
                cp16(ksa + foff + (r * HS + j) * 2, &kb[(size_t)(sf + r) * HH + j]);
                cp16(vsa + foff + (r * HS + j) * 2, &vTb[(size_t)r * TT + sf + j]);
            }
        }
        CP_COMMIT();
        __syncthreads();  // Pst visible to all warps

        // PV MMA: m=t(16/warp), n=h(32/warp), k=s(64)
#pragma unroll
        for (int k4 = 0; k4 < 4; k4++) {
            unsigned a[4], bv[2][4];
            ldsm_x4(a, pa + k4 * 32);
            ldsm_x4(bv[0], vba[0] + boff + k4 * 32);
            ldsm_x4(bv[1], vba[1] + boff + k4 * 32);
#pragma unroll
            for (int nt = 0; nt < 4; nt++)
                mma16(acc_o[nt], a, bv[nt >> 1] + (nt & 1) * 2);
        }
    }

    float* ob = out + (size_t)b * TT * HH;
    const int tr0 = t0 + tw + g, tr1 = tr0 + 8;
#pragma unroll
    for (int nt = 0; nt < 4; nt++) {
        const int h = hw + nt * 8 + 2 * tg;
        atomicAdd(&ob[(size_t)tr0 * HH + h],     acc_o[nt][0]);
        atomicAdd(&ob[(size_t)tr0 * HH + h + 1], acc_o[nt][1]);
        atomicAdd(&ob[(size_t)tr1 * HH + h],     acc_o[nt][2]);
        atomicAdd(&ob[(size_t)tr1 * HH + h + 1], acc_o[nt][3]);
    }
}

// ---------------------------------------------------------------------------
extern "C" void kernel_launch(void* const* d_in, const int* in_sizes, int n_in,
                              void* d_out, int out_size) {
    const float* x  = (const float*)d_in[0];
    const float* Wq = (const float*)d_in[1];
    const float* Wk = (const float*)d_in[2];
    const float* Wv = (const float*)d_in[3];
    float* out = (float*)d_out;

    const float scale = 1.0f / sqrtf((float)CC);

    cudaFuncSetAttribute(sumexp_kernel,
                         cudaFuncAttributeMaxDynamicSharedMemorySize, 36864);
    cudaFuncSetAttribute(attn_kernel,
                         cudaFuncAttributeMaxDynamicSharedMemorySize, 73728);

    dim3 gProj(BB * TT / 64, 3);
    proj_kernel<<<gProj, 256>>>(x, Wq, Wk, Wv);

    dim3 gSum(TT / 128, TT / 128, BB);
    sumexp_kernel<<<gSum, 256, 36864>>>(scale);

    normalize_kernel<<<512, 256>>>(out);

    dim3 gAttn(TT / 64, 4, BB);
    attn_kernel<<<gAttn, 256, 73728>>>(out, scale);
}

// round 17
// speedup vs baseline: 1.2683x; 1.2683x over previous
#include <cuda_runtime.h>
#include <cuda_fp16.h>
#include <math.h>

#define BB 8
#define TT 2048
#define CC 384
#define HH 64

// Scratch (allocation-free rule: __device__ globals)
__device__ __half g_qh[BB * TT * HH];               // 2 MB  [b][t][h]
__device__ __half g_kh[BB * TT * HH];               // 2 MB  [b][s][h]
__device__ __half g_vT[BB * HH * TT];               // 2 MB  [b][h][s], later scaled 1/Z
__device__ float  g_sum[BB * TT];                   // per-key exp sums
__device__ __half g_Ph[(size_t)BB * TT * TT];       // 67 MB unnormalized exp, [b][t][s]

// ---------------------------------------------------------------------------
// fp16 m16n8k16 MMA + ldmatrix + cp.async helpers. g = lane>>2, tg = lane&3.
//  A row-major [m][k]: a0=(g,2tg) a1=(g+8,2tg) a2=(g,2tg+8) a3=(g+8,2tg+8)
//  B col-major [n][k]: b0=(n g, k 2tg) b1=(n g, k 2tg+8)
//  C: c0=(g,2tg) c1=(g,2tg+1) c2=(g+8,2tg) c3=(g+8,2tg+1)
// ---------------------------------------------------------------------------
__device__ __forceinline__ void mma16(float* c, const unsigned* a, const unsigned* b) {
    asm("mma.sync.aligned.m16n8k16.row.col.f32.f16.f16.f32 "
        "{%0,%1,%2,%3},{%4,%5,%6,%7},{%8,%9},{%0,%1,%2,%3};"
        : "+f"(c[0]), "+f"(c[1]), "+f"(c[2]), "+f"(c[3])
        : "r"(a[0]), "r"(a[1]), "r"(a[2]), "r"(a[3]), "r"(b[0]), "r"(b[1]));
}

__device__ __forceinline__ void ldsm_x4(unsigned* r, unsigned addr) {
    asm volatile("ldmatrix.sync.aligned.m8n8.x4.shared.b16 {%0,%1,%2,%3}, [%4];"
                 : "=r"(r[0]), "=r"(r[1]), "=r"(r[2]), "=r"(r[3]) : "r"(addr));
}

__device__ __forceinline__ unsigned smaddr(const void* p) {
    return (unsigned)__cvta_generic_to_shared(p);
}

__device__ __forceinline__ void cp16(unsigned dst, const void* src) {
    asm volatile("cp.async.cg.shared.global [%0], [%1], 16;" :: "r"(dst), "l"(src));
}
#define CP_COMMIT() asm volatile("cp.async.commit_group;")
#define CP_WAIT0()  asm volatile("cp.async.wait_group 0;")
#define CP_WAIT2()  asm volatile("cp.async.wait_group 2;")

// A-operand x4 base (16 rows x 16 k): matrices (r0,k0),(r+8,k0),(r0,k+8),(r+8,k+8)
#define A_OFF(lane) ((((lane) & 7) + (((lane) >> 3) & 1) * 8) )
#define A_KOFF(lane) ((((lane) >> 4) & 1) * 8)
// B-operand x4 base (16 n-rows x 16 k): matrices (n0,k0),(n0,k+8),(n+8,k0),(n+8,k+8)
#define B_OFF(lane) ((((lane) & 7) + (((lane) >> 4) & 1) * 8))
#define B_KOFF(lane) ((((lane) >> 3) & 1) * 8)

#define HS 72   // half stride for 64-col k tiles (144 B rows, 16B aligned, cf)
#define PS 40   // half stride for 32-col k tiles (80 B rows, 16B aligned, cf)
#define QS 136  // half stride for staged 128-col P tile (272 B rows, 16B aligned)
#define VS 72   // half stride for staged v tile (coalesced uint4 rows)

// ---------------------------------------------------------------------------
// Kernel 1: fused projections, fp16 MMA, register-pipelined global fills
// (depth 2 -> LDG latency hidden behind MMA/syncs). Also zeroes g_sum.
// q -> g_qh[t][h], k -> g_kh[s][h], v -> g_vT[h][s] (staged coalesced).
// grid = (B*T/64, 3), block = 256.
// ---------------------------------------------------------------------------
__device__ __forceinline__ void proj_ldg(const float* __restrict__ x,
                                         const float* __restrict__ W,
                                         int row0, int tid, int c,
                                         float4* rx, float4* rw) {
    const int k0c = c * 32;
#pragma unroll
    for (int ii = 0; ii < 2; ii++) {
        const int i = tid + ii * 256;
        const int r = i >> 3, c4 = (i & 7) * 4;
        rx[ii] = *(const float4*)&x[(size_t)(row0 + r) * CC + k0c + c4];
        const int r2 = i >> 4, c42 = (i & 15) * 4;
        rw[ii] = *(const float4*)&W[(k0c + r2) * HH + c42];
    }
}

__device__ __forceinline__ void proj_sts(__half* xs, __half* ws, int tid,
                                         const float4* rx, const float4* rw) {
#pragma unroll
    for (int ii = 0; ii < 2; ii++) {
        const int i = tid + ii * 256;
        const int r = i >> 3, c4 = (i & 7) * 4;
        *(__half2*)&xs[r * PS + c4]     = __floats2half2_rn(rx[ii].x, rx[ii].y);
        *(__half2*)&xs[r * PS + c4 + 2] = __floats2half2_rn(rx[ii].z, rx[ii].w);
        const int r2 = i >> 4, c42 = (i & 15) * 4;
        ws[(c42 + 0) * PS + r2] = __float2half(rw[ii].x);
        ws[(c42 + 1) * PS + r2] = __float2half(rw[ii].y);
        ws[(c42 + 2) * PS + r2] = __float2half(rw[ii].z);
        ws[(c42 + 3) * PS + r2] = __float2half(rw[ii].w);
    }
}

__global__ void proj_kernel(const float* __restrict__ x,
                            const float* __restrict__ Wq,
                            const float* __restrict__ Wk,
                            const float* __restrict__ Wv) {
    __shared__ __align__(16) __half smbuf[2 * 64 * PS];  // xs | ws (vstage alias)
    __half* xs = smbuf;
    __half* ws = smbuf + 64 * PS;
    const int tid = threadIdx.x;
    if (blockIdx.y == 0 && blockIdx.x < 64)
        g_sum[blockIdx.x * 256 + tid] = 0.f;
    const float* W = (blockIdx.y == 0) ? Wq : (blockIdx.y == 1) ? Wk : Wv;
    const int row0 = blockIdx.x * 64;
    const int lane = tid & 31, wid = tid >> 5;
    const int g = lane >> 2, tg = lane & 3;
    const int mw = (wid & 1) * 32, nw = (wid >> 1) * 16;

    unsigned aab[2], bab;
    {
        const int ar = A_OFF(lane), ak = A_KOFF(lane);
        aab[0] = smaddr(&xs[(mw + ar) * PS + ak]);
        aab[1] = smaddr(&xs[(mw + 16 + ar) * PS + ak]);
        bab = smaddr(&ws[(nw + B_OFF(lane)) * PS + B_KOFF(lane)]);
    }

    float acc[2][2][4] = {};
    float4 rx0[2], rw0[2], rx1[2], rw1[2];
    proj_ldg(x, W, row0, tid, 0, rx0, rw0);
    proj_ldg(x, W, row0, tid, 1, rx1, rw1);

#pragma unroll
    for (int c2 = 0; c2 < 12; c2 += 2) {
        // ---- even chunk (regs 0) ----
        proj_sts(xs, ws, tid, rx0, rw0);
        __syncthreads();
        if (c2 + 2 < 12) proj_ldg(x, W, row0, tid, c2 + 2, rx0, rw0);
#pragma unroll
        for (int kk = 0; kk < 2; kk++) {
            unsigned a[2][4], bq[4];
            ldsm_x4(a[0], aab[0] + kk * 32);
            ldsm_x4(a[1], aab[1] + kk * 32);
            ldsm_x4(bq, bab + kk * 32);
#pragma unroll
            for (int mt = 0; mt < 2; mt++)
#pragma unroll
                for (int nt = 0; nt < 2; nt++)
                    mma16(acc[mt][nt], a[mt], bq + nt * 2);
        }
        __syncthreads();
        // ---- odd chunk (regs 1) ----
        proj_sts(xs, ws, tid, rx1, rw1);
        __syncthreads();
        if (c2 + 3 < 12) proj_ldg(x, W, row0, tid, c2 + 3, rx1, rw1);
#pragma unroll
        for (int kk = 0; kk < 2; kk++) {
            unsigned a[2][4], bq[4];
            ldsm_x4(a[0], aab[0] + kk * 32);
            ldsm_x4(a[1], aab[1] + kk * 32);
            ldsm_x4(bq, bab + kk * 32);
#pragma unroll
            for (int mt = 0; mt < 2; mt++)
#pragma unroll
                for (int nt = 0; nt < 2; nt++)
                    mma16(acc[mt][nt], a[mt], bq + nt * 2);
        }
        __syncthreads();
    }

    if (blockIdx.y < 2) {
        __half* outqk = (blockIdx.y == 0) ? g_qh : g_kh;
#pragma unroll
        for (int mt = 0; mt < 2; mt++)
#pragma unroll
            for (int rs = 0; rs < 2; rs++) {
                const int row = row0 + mw + mt * 16 + rs * 8 + g;
#pragma unroll
                for (int nt = 0; nt < 2; nt++) {
                    const int col = nw + nt * 8 + 2 * tg;
                    *(__half2*)&outqk[(size_t)row * HH + col] =
                        __floats2half2_rn(acc[mt][nt][rs * 2], acc[mt][nt][rs * 2 + 1]);
                }
            }
    } else {
        // Stage v transposed in smem (reuse smbuf), then coalesced rows out.
        __half* vstage = smbuf;  // [h 64][t 64], stride VS
#pragma unroll
        for (int mt = 0; mt < 2; mt++)
#pragma unroll
            for (int rs = 0; rs < 2; rs++) {
                const int rowl = mw + mt * 16 + rs * 8 + g;
#pragma unroll
                for (int nt = 0; nt < 2; nt++) {
                    const int col = nw + nt * 8 + 2 * tg;
                    vstage[col * VS + rowl]       = __float2half(acc[mt][nt][rs * 2]);
                    vstage[(col + 1) * VS + rowl] = __float2half(acc[mt][nt][rs * 2 + 1]);
                }
            }
        __syncthreads();
        const size_t hb = (size_t)(row0 >> 11) * HH;
        const int sbase = row0 & (TT - 1);
#pragma unroll
        for (int i = tid; i < 512; i += 256) {
            const int hr = i >> 3, j = (i & 7) * 8;
            *(uint4*)&g_vT[(hb + hr) * TT + sbase + j] = *(const uint4*)&vstage[hr * VS + j];
        }
    }
}

// ---------------------------------------------------------------------------
// Kernel 2: scores, fp16 MMA + ldmatrix, 128x128 tiles, cp.async fills.
// P[t][s] = exp (half, 0 where t<s); Z[s] += row sums. m=t, n=s, k=h.
// Epilogue stages P in smem, writes coalesced uint4 rows.
// grid = (T/128, T/128, B), block 256, dyn smem 36864B (2 blocks/SM).
// ---------------------------------------------------------------------------
__global__ void __launch_bounds__(256, 2) scores_kernel(float scale) {
    const int t0 = blockIdx.x * 128;
    const int s0 = blockIdx.y * 128;
    if (t0 + 127 < s0) return;
    const int b = blockIdx.z;
    extern __shared__ __align__(16) __half sm[];
    __half* qs = sm;              // [128][HS]
    __half* ks = sm + 128 * HS;   // [128][HS]
    const __half* qb = g_qh + (size_t)b * TT * HH;
    const __half* kb = g_kh + (size_t)b * TT * HH;
    const int tid = threadIdx.x;
    const unsigned qsa = smaddr(qs), ksa = smaddr(ks);
#pragma unroll
    for (int i = tid; i < 1024; i += 256) {
        int r = i >> 3, j = (i & 7) * 8;
        cp16(qsa + (r * HS + j) * 2, &qb[(size_t)(t0 + r) * HH + j]);
        cp16(ksa + (r * HS + j) * 2, &kb[(size_t)(s0 + r) * HH + j]);
    }
    CP_COMMIT();
    CP_WAIT0();
    __syncthreads();
    const int lane = tid & 31, wid = tid >> 5;
    const int g = lane >> 2, tg = lane & 3;
    const int tw = (wid & 1) * 64, sw = (wid >> 1) * 32;

    unsigned aab[4], bab[2];
    {
        const int ar = A_OFF(lane), ak = A_KOFF(lane);
        const int br = B_OFF(lane), bk = B_KOFF(lane);
#pragma unroll
        for (int mt = 0; mt < 4; mt++)
            aab[mt] = smaddr(&qs[(tw + mt * 16 + ar) * HS + ak]);
#pragma unroll
        for (int np = 0; np < 2; np++)
            bab[np] = smaddr(&ks[(sw + np * 16 + br) * HS + bk]);
    }

    float acc[4][4][4] = {};  // [mt(t)][nt(s)][4]
#pragma unroll
    for (int k4 = 0; k4 < 4; k4++) {
        unsigned a[4][4], bq[2][4];
#pragma unroll
        for (int mt = 0; mt < 4; mt++) ldsm_x4(a[mt], aab[mt] + k4 * 32);
#pragma unroll
        for (int np = 0; np < 2; np++) ldsm_x4(bq[np], bab[np] + k4 * 32);
#pragma unroll
        for (int mt = 0; mt < 4; mt++)
#pragma unroll
            for (int nt = 0; nt < 4; nt++)
                mma16(acc[mt][nt], a[mt], bq[nt >> 1] + (nt & 1) * 2);
    }
    __syncthreads();  // q/k tiles dead; reuse smem to stage P

    // Epilogue: exp + mask into staged smem P tile [128][QS]; Z partial sums.
    __half* Pst = sm;
    float* Zb = g_sum + b * TT;
    float zc[4][2] = {};
#pragma unroll
    for (int mt = 0; mt < 4; mt++)
#pragma unroll
        for (int rs = 0; rs < 2; rs++) {
            const int tl = tw + mt * 16 + rs * 8 + g;
            const int t = t0 + tl;
#pragma unroll
            for (int nt = 0; nt < 4; nt++) {
                const int sl = sw + nt * 8 + 2 * tg;
                const int s = s0 + sl;
                float e0 = (t >= s) ? __expf(acc[mt][nt][rs * 2] * scale)     : 0.f;
                float e1 = (t >  s) ? __expf(acc[mt][nt][rs * 2 + 1] * scale) : 0.f;
                *(__half2*)&Pst[tl * QS + sl] = __floats2half2_rn(e0, e1);
                zc[nt][0] += e0; zc[nt][1] += e1;
            }
        }
#pragma unroll
    for (int nt = 0; nt < 4; nt++) {
        float z0 = zc[nt][0], z1 = zc[nt][1];
#pragma unroll
        for (int o = 4; o < 32; o <<= 1) {
            z0 += __shfl_xor_sync(0xffffffffu, z0, o);
            z1 += __shfl_xor_sync(0xffffffffu, z1, o);
        }
        if (g == 0) {
            const int s = s0 + sw + nt * 8 + 2 * tg;
            atomicAdd(&Zb[s], z0);
            atomicAdd(&Zb[s + 1], z1);
        }
    }
    __syncthreads();  // P staged

    // Coalesced write: 128 rows x 256B, uint4 per thread-iter.
    __half* Pb = g_Ph + (size_t)b * TT * TT;
#pragma unroll
    for (int i = tid; i < 2048; i += 256) {
        int r = i >> 4, c = (i & 15) * 8;
        *(uint4*)&Pb[(size_t)(t0 + r) * TT + s0 + c] = *(const uint4*)&Pst[r * QS + c];
    }
}

// ---------------------------------------------------------------------------
// Kernel 3: scale vT in place by 1/Z[s]; also zeroes d_out for pv's atomics.
// grid = 512, block = 256 (one uint4 = 8 halves per thread).
// ---------------------------------------------------------------------------
__global__ void normalize_kernel(float* __restrict__ out) {
    const int u = blockIdx.x * 256 + threadIdx.x;   // uint4 index
    const float4 z = make_float4(0.f, 0.f, 0.f, 0.f);
    ((float4*)out)[u * 2]     = z;
    ((float4*)out)[u * 2 + 1] = z;
    const int hl = u * 8;
    const int bh = hl >> 11;            // b*64 + h
    const int s = hl & (TT - 1);
    const float* Zp = g_sum + ((bh >> 6) << 11) + s;
    uint4 val = *(uint4*)&g_vT[(size_t)bh * TT + s];
    __half2* hp = (__half2*)&val;
    const float4 z0 = *(const float4*)&Zp[0];
    const float4 z1 = *(const float4*)&Zp[4];
    float2 f;
    f = __half22float2(hp[0]);
    hp[0] = __floats2half2_rn(f.x * __frcp_rn(z0.x), f.y * __frcp_rn(z0.y));
    f = __half22float2(hp[1]);
    hp[1] = __floats2half2_rn(f.x * __frcp_rn(z0.z), f.y * __frcp_rn(z0.w));
    f = __half22float2(hp[2]);
    hp[2] = __floats2half2_rn(f.x * __frcp_rn(z1.x), f.y * __frcp_rn(z1.y));
    f = __half22float2(hp[3]);
    hp[3] = __floats2half2_rn(f.x * __frcp_rn(z1.z), f.y * __frcp_rn(z1.w));
    *(uint4*)&g_vT[(size_t)bh * TT + s] = val;
}

// ---------------------------------------------------------------------------
// pv async tile fill: cp.async 16B, no register round-trip.
// ---------------------------------------------------------------------------
__device__ __forceinline__ void fill_pv_async(const __half* __restrict__ Pb,
                                              const __half* __restrict__ vTb,
                                              unsigned Psb, unsigned vsb,
                                              int t0, int s0, int tid) {
#pragma unroll
    for (int i = tid; i < 512; i += 256) {
        int r = i >> 3, j = (i & 7) * 8;
        cp16(Psb + (r * HS + j) * 2, &Pb[(size_t)(t0 + r) * TT + s0 + j]);
        cp16(vsb + (r * HS + j) * 2, &vTb[(size_t)r * TT + s0 + j]);
    }
}

// ---------------------------------------------------------------------------
// Kernel 4: out[t][h] += sum_s P[t][s] * vT[h][s] (vT pre-scaled by 1/Z).
// fp16 MMA + ldmatrix, 4-stage cp.async pipeline (wait_group 2), 3 blocks/SM.
// grid = (T/64, 4 s-chunks of 8 tiles, B), block 256, dyn smem 73728B.
// Warps: 4 t-groups (16 rows) x 2 h-groups (32 cols).
// One commit per iteration (possibly empty) keeps the wait count uniform.
// ---------------------------------------------------------------------------
#define PVST 4
__global__ void __launch_bounds__(256, 3) pv_kernel(float* __restrict__ out) {
    const int tt = blockIdx.x;
    const int chunk0 = blockIdx.y * 8;
    if (chunk0 > tt) return;
    const int t0 = tt * 64;
    const int b = blockIdx.z;
    const __half* Pb = g_Ph + (size_t)b * TT * TT;
    const __half* vTb = g_vT + (size_t)b * HH * TT;
    extern __shared__ __align__(16) __half sm[];
    __half* Ps = sm;                    // PVST x [64][HS]
    __half* vs = sm + PVST * 64 * HS;   // PVST x [64][HS]
    const unsigned Psa = smaddr(Ps), vsa = smaddr(vs);
    const unsigned BUF = 64 * HS * 2;   // bytes per stage
    const int tid = threadIdx.x;
    const int lane = tid & 31, wid = tid >> 5;
    const int g = lane >> 2, tg = lane & 3;
    const int tw = (wid >> 1) * 16;
    const int hw = (wid & 1) * 32;

    unsigned aab, bab[2];
    {
        const int ar = A_OFF(lane), ak = A_KOFF(lane);
        const int br = B_OFF(lane), bk = B_KOFF(lane);
        aab = smaddr(&Ps[(tw + ar) * HS + ak]);
        bab[0] = smaddr(&vs[(hw + br) * HS + bk]);
        bab[1] = smaddr(&vs[(hw + 16 + br) * HS + bk]);
    }

    float acc[4][4] = {};  // [nt(h)][4]
    const int n = min(chunk0 + 8, tt + 1) - chunk0;

    fill_pv_async(Pb, vTb, Psa, vsa, t0, chunk0 * 64, tid);
    CP_COMMIT();
    if (n > 1)
        fill_pv_async(Pb, vTb, Psa + BUF, vsa + BUF, t0, (chunk0 + 1) * 64, tid);
    CP_COMMIT();
    if (n > 2)
        fill_pv_async(Pb, vTb, Psa + 2 * BUF, vsa + 2 * BUF, t0, (chunk0 + 2) * 64, tid);
    CP_COMMIT();

    for (int st = 0; st < n; st++) {
        CP_WAIT2();
        __syncthreads();
        const unsigned boff = (unsigned)(st % PVST) * BUF;
#pragma unroll
        for (int k4 = 0; k4 < 4; k4++) {
            unsigned a[4], bq[2][4];
            ldsm_x4(a, aab + boff + k4 * 32);
            ldsm_x4(bq[0], bab[0] + boff + k4 * 32);
            ldsm_x4(bq[1], bab[1] + boff + k4 * 32);
#pragma unroll
            for (int nt = 0; nt < 4; nt++)
                mma16(acc[nt], a, bq[nt >> 1] + (nt & 1) * 2);
        }
        if (st + 3 < n) {
            const unsigned foff = (unsigned)((st + 3) % PVST) * BUF;
            fill_pv_async(Pb, vTb, Psa + foff, vsa + foff,
                          t0, (chunk0 + st + 3) * 64, tid);
        }
        CP_COMMIT();
    }

    float* ob = out + (size_t)b * TT * HH;
    const int tr0 = t0 + tw + g, tr1 = tr0 + 8;
#pragma unroll
    for (int nt = 0; nt < 4; nt++) {
        const int h = hw + nt * 8 + 2 * tg;
        atomicAdd(&ob[(size_t)tr0 * HH + h],     acc[nt][0]);
        atomicAdd(&ob[(size_t)tr0 * HH + h + 1], acc[nt][1]);
        atomicAdd(&ob[(size_t)tr1 * HH + h],     acc[nt][2]);
        atomicAdd(&ob[(size_t)tr1 * HH + h + 1], acc[nt][3]);
    }
}

// ---------------------------------------------------------------------------
extern "C" void kernel_launch(void* const* d_in, const int* in_sizes, int n_in,
                              void* d_out, int out_size) {
    const float* x  = (const float*)d_in[0];
    const float* Wq = (const float*)d_in[1];
    const float* Wk = (const float*)d_in[2];
    const float* Wv = (const float*)d_in[3];
    float* out = (float*)d_out;

    const float scale = 1.0f / sqrtf((float)CC);

    cudaFuncSetAttribute(scores_kernel,
                         cudaFuncAttributeMaxDynamicSharedMemorySize, 36864);
    cudaFuncSetAttribute(pv_kernel,
                         cudaFuncAttributeMaxDynamicSharedMemorySize, 73728);

    dim3 gProj(BB * TT / 64, 3);
    proj_kernel<<<gProj, 256>>>(x, Wq, Wk, Wv);

    dim3 gScores(TT / 128, TT / 128, BB);
    scores_kernel<<<gScores, 256, 36864>>>(scale);

    normalize_kernel<<<512, 256>>>(out);

    dim3 gPV(TT / 64, 4, BB);
    pv_kernel<<<gPV, 256, 73728>>>(out);
}